// round 12
// baseline (speedup 1.0000x reference)
#include <cuda_runtime.h>

// FWHT (11 stages, N=2048) + sign flip on last quarter, batch 16384.
// FOUR warps per row, 16 fp32/thread (k = K3K2K1K0), warp quarter q = i9,i10.
//
// Initial bits: i0,i1=K0,K1 ; i2..i6=lane ; i7,i8=K2,K3 ; i9,i10=q.
// Plan: radix4(K0,K1) ; radix4(K2,K3) ; 5 swap-shuffle stages for lane bits
// (1 SHFL per register pair; stage s swaps lane bit h=1<<s with register bit
//  m = h for s<4, m = 1 for s=4 — register bits are reused after their index
//  bit has been butterflied).
// Final per-warp layout: i = L0 +2L1 +4L4 +8K1 +16K2 +32K3 +64K0 +128L2 +256L3.
// One padded smem scatter repairs the layout AND feeds a radix-4 butterfly
// across the 4 warps (bits 9,10), fused with sign (q==3) + 2^-5.5 scale +
// coalesced STG.128.

__global__ void __launch_bounds__(256, 6)
fwht_sign_kernel4(const float* __restrict__ in, float* __restrict__ out, int rows) {
    // 2 rows/block x 4 quarters x (512 + 8-per-128 pad) floats = 16.75 KB
    __shared__ float sbuf[2][4][536];

    const int warp     = threadIdx.x >> 5;
    const int lane     = threadIdx.x & 31;
    const int rowLocal = warp >> 2;          // 0..1
    const int q        = warp & 3;           // input bits 9,10
    const int row      = blockIdx.x * 2 + rowLocal;
    const bool active  = (row < rows);

    float v[16];

    if (active) {
        const float4* __restrict__ src =
            reinterpret_cast<const float4*>(in) + (size_t)row * 512 + q * 128;

        // Coalesced load: 4 x float4 per thread (512B contiguous per warp instr).
        #pragma unroll
        for (int r = 0; r < 4; r++) {
            float4 f = src[r * 32 + lane];
            v[4*r+0] = f.x; v[4*r+1] = f.y; v[4*r+2] = f.z; v[4*r+3] = f.w;
        }

        // Bits 0,1: radix-4 on K0,K1 (inside each float4).
        #pragma unroll
        for (int b = 0; b < 16; b += 4) {
            float a0 = v[b+0], a1 = v[b+1], a2 = v[b+2], a3 = v[b+3];
            float t0 = a0 + a1, t1 = a0 - a1, t2 = a2 + a3, t3 = a2 - a3;
            v[b+0] = t0 + t2;
            v[b+1] = t1 + t3;
            v[b+2] = t0 - t2;
            v[b+3] = t1 - t3;
        }

        // Bits 7,8: radix-4 on K2,K3.
        #pragma unroll
        for (int k = 0; k < 4; k++) {
            float a = v[k], b = v[k+4], c = v[k+8], d = v[k+12];
            float t0 = a + b, t1 = a - b, t2 = c + d, t3 = c - d;
            v[k+0]  = t0 + t2;
            v[k+4]  = t1 + t3;
            v[k+8]  = t0 - t2;
            v[k+12] = t1 - t3;
        }

        // Bits 2..6: swap-shuffle stages (8 SHFL per stage).
        #pragma unroll
        for (int s = 0; s < 5; s++) {
            const int  h  = 1 << s;            // lane bit being butterflied
            const int  m  = (s < 4) ? h : 1;   // register partner bit
            const bool up = (lane & h) != 0;
            #pragma unroll
            for (int k = 0; k < 16; k++) {
                if (k & m) continue;
                const int ko = k | m;
                float send = up ? v[k] : v[ko];
                float t = __shfl_xor_sync(0xffffffffu, send, h);
                float a = up ? t     : v[k];
                float b = up ? v[ko] : t;
                v[k]  = a + b;
                v[ko] = a - b;
            }
        }

        // Scatter to smem in linear sub-index order (padded, conflict-free).
        // j = (lane&3) + 4*L4 + 8*K1 + 16*K2 + 32*K3 + 64*K0 + 128*L2 + 256*L3
        {
            float* sb = sbuf[rowLocal][q];
            const int jbase = (lane & 3) | (((lane >> 4) & 1) << 2)
                            | (((lane >> 2) & 3) << 7);
            const int pbase = jbase + 8 * (jbase >> 7);   // +8 floats per 128
            #pragma unroll
            for (int k = 0; k < 16; k++) {
                const int joff = ((k >> 1) << 3) | ((k & 1) << 6);
                sb[pbase + joff] = v[k];   // banks = full 32-lane permutation
            }
        }
    }

    // Sync the 4 warps of this row only (128 threads), barrier id 1 or 2.
    asm volatile("bar.sync %0, 128;" :: "r"(rowLocal + 1) : "memory");

    if (active) {
        const float* b0 = sbuf[rowLocal][0];
        const float* b1 = sbuf[rowLocal][1];
        const float* b2 = sbuf[rowLocal][2];
        const float* b3 = sbuf[rowLocal][3];
        float4* __restrict__ dst =
            reinterpret_cast<float4*>(out) + (size_t)row * 512 + q * 128;

        const float S   = 0.022097086912079612f;     // (1/sqrt(2))^11
        const float sq  = (q == 3) ? -S : S;         // fold last-quarter flip
        const float sg1 = (q & 1) ? -1.0f : 1.0f;    // output bit 9
        const float sg2 = (q & 2) ? -1.0f : 1.0f;    // output bit 10

        // Radix-4 across quarters (bits 9,10) + scale + coalesced store.
        #pragma unroll
        for (int g = 0; g < 4; g++) {
            const int a = g * 136 + 4 * lane;        // padded addr, LDS.128 clean
            float4 A0 = *reinterpret_cast<const float4*>(b0 + a);
            float4 A1 = *reinterpret_cast<const float4*>(b1 + a);
            float4 A2 = *reinterpret_cast<const float4*>(b2 + a);
            float4 A3 = *reinterpret_cast<const float4*>(b3 + a);
            float4 o;
            o.x = (fmaf(sg2, fmaf(sg1, A3.x, A2.x), fmaf(sg1, A1.x, A0.x))) * sq;
            o.y = (fmaf(sg2, fmaf(sg1, A3.y, A2.y), fmaf(sg1, A1.y, A0.y))) * sq;
            o.z = (fmaf(sg2, fmaf(sg1, A3.z, A2.z), fmaf(sg1, A1.z, A0.z))) * sq;
            o.w = (fmaf(sg2, fmaf(sg1, A3.w, A2.w), fmaf(sg1, A1.w, A0.w))) * sq;
            dst[g * 32 + lane] = o;
        }
    }
}

extern "C" void kernel_launch(void* const* d_in, const int* in_sizes, int n_in,
                              void* d_out, int out_size) {
    const float* x = (const float*)d_in[0];
    float* out = (float*)d_out;
    const int rows   = in_sizes[0] / 2048;     // 16384
    const int blocks = (rows + 1) / 2;         // 2 rows per 256-thread block
    fwht_sign_kernel4<<<blocks, 256>>>(x, out, rows);
}

// round 13
// speedup vs baseline: 1.0137x; 1.0137x over previous
#include <cuda_runtime.h>

// FWHT (11 stages, N=2048) + sign flip on last quarter, batch 16384.
// kernel3 dataflow (2 warps/row, 32 fp32/thread, swap-shuffles, one smem
// half-exchange) wrapped in a PERSISTENT grid-stride loop with register
// prefetch of the next row, so each warp always has 8 LDG.128 in flight and
// DRAM never idles during the compute/smem phases.
//
// Bits: i0,i1=k0,k1 ; i2..i6=lane ; i7,i8,i9=k2,k3,k4 ; i10=warp half.
//   1) radix-4 on k0,k1            (register-local)
//   2) butterflies on k2,k3,k4     (register-local)
//   3) 5 swap-shuffle stages for lane bits (1 SHFL per register pair)
//   4) STS scrambled->linear (padded), named barrier (warp pair),
//      LDS both halves + bit-10 butterfly + sign/scale + coalesced STG.128,
//      named barrier (smem reuse).

__global__ void __launch_bounds__(256, 3)
fwht_sign_kernel5(const float* __restrict__ in, float* __restrict__ out, int rows) {
    __shared__ float sbuf[8][1056];          // 4 pairs x 2 halves x (1024+32 pad)

    const int warp     = threadIdx.x >> 5;
    const int lane     = threadIdx.x & 31;
    const int pairLoc  = warp >> 1;          // 0..3
    const int half     = warp & 1;           // index bit 10
    const int pairGlb  = blockIdx.x * 4 + pairLoc;
    const int pairStr  = gridDim.x * 4;

    // Precomputed smem addressing for the scrambled scatter.
    float* sbOwn = sbuf[pairLoc * 2 + half];
    const float* slo = sbuf[pairLoc * 2 + 0];
    const float* shi = sbuf[pairLoc * 2 + 1];
    const int scatBase = (lane & 3) + (lane >> 2) * 132;

    const float S = 0.022097086912079612f;   // (1/sqrt(2))^11

    float4 pf[8];
    int row = pairGlb;
    if (row < rows) {
        const float4* src = reinterpret_cast<const float4*>(in)
                          + (size_t)row * 512 + half * 256;
        #pragma unroll
        for (int r = 0; r < 8; r++) pf[r] = src[r * 32 + lane];
    }

    for (; row < rows; row += pairStr) {
        // Unpack prefetched row into working registers.
        float v[32];
        #pragma unroll
        for (int r = 0; r < 8; r++) {
            v[4*r+0] = pf[r].x; v[4*r+1] = pf[r].y;
            v[4*r+2] = pf[r].z; v[4*r+3] = pf[r].w;
        }

        // Prefetch next row (loads drain under the compute below).
        const int nrow = row + pairStr;
        if (nrow < rows) {
            const float4* nsrc = reinterpret_cast<const float4*>(in)
                               + (size_t)nrow * 512 + half * 256;
            #pragma unroll
            for (int r = 0; r < 8; r++) pf[r] = nsrc[r * 32 + lane];
        }

        // Bits 0,1: radix-4 inside each float4.
        #pragma unroll
        for (int q = 0; q < 32; q += 4) {
            float a0 = v[q+0], a1 = v[q+1], a2 = v[q+2], a3 = v[q+3];
            float b0 = a0 + a1, b1 = a0 - a1, b2 = a2 + a3, b3 = a2 - a3;
            v[q+0] = b0 + b2;
            v[q+1] = b1 + b3;
            v[q+2] = b0 - b2;
            v[q+3] = b1 - b3;
        }

        // Bits 7,8,9: register-local butterflies (bits k2,k3,k4).
        #pragma unroll
        for (int m = 4; m <= 16; m <<= 1) {
            #pragma unroll
            for (int k = 0; k < 32; k++) {
                if (k & m) continue;
                float a = v[k], b = v[k|m];
                v[k]   = a + b;
                v[k|m] = a - b;
            }
        }

        // Bits 2..6: swap-shuffle stages (1 SHFL per register pair).
        #pragma unroll
        for (int s = 0; s < 5; s++) {
            const int  h  = 1 << s;
            const bool up = (lane & h) != 0;
            #pragma unroll
            for (int k = 0; k < 32; k++) {
                if (k & h) continue;
                const int ko = k | h;
                float send = up ? v[k] : v[ko];
                float t = __shfl_xor_sync(0xffffffffu, send, h);
                float a = up ? t     : v[k];
                float b = up ? v[ko] : t;
                v[k]  = a + b;
                v[ko] = a - b;
            }
        }

        // Publish own half to smem, undoing the scramble (padded, conflict-free).
        // idx = (lane&3) | (k<<2) | ((lane>>2)<<7); addr = idx + 4*(idx>>7).
        #pragma unroll
        for (int k = 0; k < 32; k++)
            sbOwn[scatBase + 4 * k] = v[k];

        asm volatile("bar.sync %0, 64;" :: "r"(pairLoc + 1) : "memory");

        // Bit-10 butterfly + sign + scale + coalesced store.
        {
            float4* dst = reinterpret_cast<float4*>(out)
                        + (size_t)row * 512 + half * 256;
            #pragma unroll
            for (int g = 0; g < 8; g++) {
                const int a = g * 132 + lane * 4;      // conflict-free LDS.128
                float4 lo = *reinterpret_cast<const float4*>(slo + a);
                float4 hi = *reinterpret_cast<const float4*>(shi + a);
                const float s = (half == 1 && g >= 4) ? -S : S;
                float4 o;
                if (half == 0) {
                    o.x = (lo.x + hi.x) * s; o.y = (lo.y + hi.y) * s;
                    o.z = (lo.z + hi.z) * s; o.w = (lo.w + hi.w) * s;
                } else {
                    o.x = (lo.x - hi.x) * s; o.y = (lo.y - hi.y) * s;
                    o.z = (lo.z - hi.z) * s; o.w = (lo.w - hi.w) * s;
                }
                dst[g * 32 + lane] = o;
            }
        }

        // Protect smem buffer before next iteration's scatter.
        asm volatile("bar.sync %0, 64;" :: "r"(pairLoc + 1) : "memory");
    }
}

extern "C" void kernel_launch(void* const* d_in, const int* in_sizes, int n_in,
                              void* d_out, int out_size) {
    const float* x = (const float*)d_in[0];
    float* out = (float*)d_out;
    const int rows = in_sizes[0] / 2048;     // 16384
    // Persistent grid: 148 SMs x 3 blocks (launch_bounds min), grid-stride loop.
    const int blocks = 148 * 3;
    fwht_sign_kernel5<<<blocks, 256>>>(x, out, rows);
}